// round 9
// baseline (speedup 1.0000x reference)
#include <cuda_runtime.h>
#include <cuda_bf16.h>

// MultiHeadSpMM: out[r, h*D+d] = sum_{e: row[e]==r} attention[e,h] * h[col[e],h,d]
// N=100000, E=1600000, H=4, D=8 (H*D == 32). row[] is sorted.
//
// R9: warp-per-row, shfl-broadcast, barrier-free.
//   lane = output feature f (head h = f>>3). Per 8-edge batch:
//     - lane 8h+q loads att[(b+q)*4+h]  (128B contiguous -> 1 L1 wavefront)
//     - lane loads col[b + (lane&7)]    (32B -> 1 wavefront)
//     - per edge k: c = shfl(col,k); a = shfl(att,(lane&24)|k);
//       v = LDG hfeat[c*32+lane]  (32 consecutive floats = ONE 128B line);
//       acc = fma(a,v,acc).
//   8 independent gathers in flight per warp; no smem, no barriers,
//   no per-edge predication ALU (tail edges have a=0).

#define MAX_NODES (1 << 21)

__device__ int g_row_ptr[MAX_NODES + 1];

__global__ void build_row_ptr_kernel(const int* __restrict__ row, int E, int N) {
    int e = blockIdx.x * blockDim.x + threadIdx.x;
    if (e >= E) return;
    int r = row[e];
    if (r < 0) r = 0;
    if (r >= N) r = N - 1;
    int prev;
    if (e == 0) {
        prev = -1;
    } else {
        prev = row[e - 1];
        if (prev < 0) prev = 0;
        if (prev >= N) prev = N - 1;
    }
    for (int i = prev + 1; i <= r; ++i) g_row_ptr[i] = e;
    if (e == E - 1) {
        for (int i = r + 1; i <= N; ++i) g_row_ptr[i] = E;
    }
}

__global__ __launch_bounds__(256) void spmm_shfl_kernel(
    const int* __restrict__ col,
    const float* __restrict__ att,   // (E, 4)
    const float* __restrict__ hfeat, // (N, 32)
    float* __restrict__ out,         // (N, 32)
    int N)
{
    const unsigned FULL = 0xffffffffu;
    int warp = (blockIdx.x * blockDim.x + threadIdx.x) >> 5;
    int lane = threadIdx.x & 31;
    if (warp >= N) return;

    const int beg = g_row_ptr[warp];
    const int end = g_row_ptr[warp + 1];

    const int q = lane & 7;        // edge slot within batch
    const int h = lane >> 3;       // head owned by this lane's att_reg slot
    const int asrc = lane & 24;    // shfl source base (= 8*my_head)
    const int nmax = N - 1;

    float acc = 0.0f;

    for (int b = beg; b < end; b += 8) {
        int eq = b + q;
        bool vq = (eq < end);
        int es = vq ? eq : beg;            // safe address (beg<end inside loop)

        int   cq = __ldg(&col[es]);
        cq = min(max(cq, 0), nmax);
        cq = vq ? cq : 0;                  // tail -> gather node 0 (a will be 0)
        float aq = vq ? __ldg(&att[es * 4 + h]) : 0.f;

        #pragma unroll
        for (int k = 0; k < 8; ++k) {
            int   c = __shfl_sync(FULL, cq, k);
            float a = __shfl_sync(FULL, aq, asrc | k);
            float v = __ldg(&hfeat[c * 32 + lane]);   // one 128B line
            acc = fmaf(a, v, acc);
        }
    }

    out[warp * 32 + lane] = acc;   // coalesced 128B per warp; zeros for empty rows
}

extern "C" void kernel_launch(void* const* d_in, const int* in_sizes, int n_in,
                              void* d_out, int out_size) {
    const int*   row  = (const int*)  d_in[0];
    const int*   col  = (const int*)  d_in[1];
    const float* att  = (const float*)d_in[2];
    const float* hft  = (const float*)d_in[3];
    float*       out  = (float*)      d_out;

    int E = in_sizes[0];
    int N = in_sizes[3] / 32;  // h is (N, 4, 8)

    {
        int threads = 256;
        int blocks = (E + threads - 1) / threads;
        build_row_ptr_kernel<<<blocks, threads>>>(row, E, N);
    }
    {
        int threads = 256;  // 8 warps per block, one warp per row
        int blocks = (N * 32 + threads - 1) / threads;
        spmm_shfl_kernel<<<blocks, threads>>>(col, att, hft, out, N);
    }
}

// round 10
// speedup vs baseline: 1.7354x; 1.7354x over previous
#include <cuda_runtime.h>
#include <cuda_bf16.h>

// MultiHeadSpMM: out[r, h*D+d] = sum_{e: row[e]==r} attention[e,h] * h[col[e],h,d]
// N=100000, E=1600000, H=4, D=8 (H*D == 32). row[] is sorted.
//
// R10: group-per-row with NATURAL DIVERGENCE (R6 minus predication ALU).
//   Each warp owns 4 rows (group g = lane>>3 -> row 4*warp+g), lane q = lane&7
//   holds features [4q,4q+4) as a float4. Each group runs its own loop bounds;
//   the HW serializes divergent groups (cost = max group degree, same as the
//   old dmax loop) but with zero select/clamp/bool overhead per iteration and
//   no __reduce_max_sync. No smem, no shuffles, no barriers.

#define MAX_NODES (1 << 21)

__device__ int g_row_ptr[MAX_NODES + 1];

__global__ void build_row_ptr_kernel(const int* __restrict__ row, int E, int N) {
    int e = blockIdx.x * blockDim.x + threadIdx.x;
    if (e >= E) return;
    int r = row[e];
    if (r < 0) r = 0;
    if (r >= N) r = N - 1;
    int prev;
    if (e == 0) {
        prev = -1;
    } else {
        prev = row[e - 1];
        if (prev < 0) prev = 0;
        if (prev >= N) prev = N - 1;
    }
    for (int i = prev + 1; i <= r; ++i) g_row_ptr[i] = e;
    if (e == E - 1) {
        for (int i = r + 1; i <= N; ++i) g_row_ptr[i] = E;
    }
}

__global__ __launch_bounds__(256) void spmm_group_div_kernel(
    const int* __restrict__ col,
    const float* __restrict__ att,   // (E, 4)
    const float* __restrict__ hfeat, // (N, 32)
    float* __restrict__ out,         // (N, 32)
    int N)
{
    int warp = (blockIdx.x * blockDim.x + threadIdx.x) >> 5;
    int lane = threadIdx.x & 31;

    const int g  = lane >> 3;       // group 0..3 -> row
    const int q  = lane & 7;        // feature quarter
    const int hd = q >> 1;          // head for this quarter
    const int r  = warp * 4 + g;
    if (r >= N) return;             // no sync/shfl below: early exit is safe

    const int beg = g_row_ptr[r];
    const int end = g_row_ptr[r + 1];
    const int nmax = N - 1;

    float4 acc = make_float4(0.f, 0.f, 0.f, 0.f);

    int e = beg;
    // Unpredicated 4-edge unroll; groups diverge naturally.
    for (; e + 3 < end; e += 4) {
        int c0 = __ldg(&col[e]);
        int c1 = __ldg(&col[e + 1]);
        int c2 = __ldg(&col[e + 2]);
        int c3 = __ldg(&col[e + 3]);
        c0 = min(max(c0, 0), nmax);
        c1 = min(max(c1, 0), nmax);
        c2 = min(max(c2, 0), nmax);
        c3 = min(max(c3, 0), nmax);

        float a0 = __ldg(&att[(e    ) * 4 + hd]);
        float a1 = __ldg(&att[(e + 1) * 4 + hd]);
        float a2 = __ldg(&att[(e + 2) * 4 + hd]);
        float a3 = __ldg(&att[(e + 3) * 4 + hd]);

        float4 h0 = __ldg((const float4*)(hfeat + c0 * 32 + q * 4));
        float4 h1 = __ldg((const float4*)(hfeat + c1 * 32 + q * 4));
        float4 h2 = __ldg((const float4*)(hfeat + c2 * 32 + q * 4));
        float4 h3 = __ldg((const float4*)(hfeat + c3 * 32 + q * 4));

        acc.x = fmaf(a0, h0.x, acc.x);
        acc.y = fmaf(a0, h0.y, acc.y);
        acc.z = fmaf(a0, h0.z, acc.z);
        acc.w = fmaf(a0, h0.w, acc.w);
        acc.x = fmaf(a1, h1.x, acc.x);
        acc.y = fmaf(a1, h1.y, acc.y);
        acc.z = fmaf(a1, h1.z, acc.z);
        acc.w = fmaf(a1, h1.w, acc.w);
        acc.x = fmaf(a2, h2.x, acc.x);
        acc.y = fmaf(a2, h2.y, acc.y);
        acc.z = fmaf(a2, h2.z, acc.z);
        acc.w = fmaf(a2, h2.w, acc.w);
        acc.x = fmaf(a3, h3.x, acc.x);
        acc.y = fmaf(a3, h3.y, acc.y);
        acc.z = fmaf(a3, h3.z, acc.z);
        acc.w = fmaf(a3, h3.w, acc.w);
    }
    // Scalar tail (<=3 iterations), also divergent.
    for (; e < end; ++e) {
        int c = __ldg(&col[e]);
        c = min(max(c, 0), nmax);
        float a = __ldg(&att[e * 4 + hd]);
        float4 h0 = __ldg((const float4*)(hfeat + c * 32 + q * 4));
        acc.x = fmaf(a, h0.x, acc.x);
        acc.y = fmaf(a, h0.y, acc.y);
        acc.z = fmaf(a, h0.z, acc.z);
        acc.w = fmaf(a, h0.w, acc.w);
    }

    // Warp stores 4 rows * 32 floats = 512B contiguous; zeros for empty rows.
    ((float4*)out)[r * 8 + q] = acc;
}

extern "C" void kernel_launch(void* const* d_in, const int* in_sizes, int n_in,
                              void* d_out, int out_size) {
    const int*   row  = (const int*)  d_in[0];
    const int*   col  = (const int*)  d_in[1];
    const float* att  = (const float*)d_in[2];
    const float* hft  = (const float*)d_in[3];
    float*       out  = (float*)      d_out;

    int E = in_sizes[0];
    int N = in_sizes[3] / 32;  // h is (N, 4, 8)

    {
        int threads = 256;
        int blocks = (E + threads - 1) / threads;
        build_row_ptr_kernel<<<blocks, threads>>>(row, E, N);
    }
    {
        int threads = 256;                     // 8 warps = 32 rows per block
        int rows_per_block = (threads / 32) * 4;
        int blocks = (N + rows_per_block - 1) / rows_per_block;
        spmm_group_div_kernel<<<blocks, threads>>>(col, att, hft, out, N);
    }
}